// round 4
// baseline (speedup 1.0000x reference)
#include <cuda_runtime.h>
#include <cuda_bf16.h>

// Problem constants (fixed shapes per reference setup_inputs)
#define BATCH 32
#define IMG_H 512
#define IMG_W 512
#define IMG_C 3
#define KPTS 16
#define NE 19                 // K + 3
#define NPIX (IMG_H * IMG_W)  // 262144

// Numerics contract (must replicate the reference's XLA:GPU fp32 semantics):
//  - einsum1 'bpk,ek->bpe' (tiny): NOT a cuBLAS gemm -> decomposed
//    multiply+reduce, NO fp contraction: round each product, then
//    sequential ascending adds from 0.           (__fmul_rn/__fadd_rn)
//  - einsum2 'bpe,en->bpn' (big):  cuBLAS fp32 -> sequential ascending
//    FFMA, accumulator init 0.                   (fmaf)
//  - final bilinear blend: fused elementwise, no contraction ->
//    left-assoc mul/add.                         (__fmul_rn/__fadd_rn)
__global__ __launch_bounds__(256) void tps_warp_kernel(
    const float* __restrict__ image,         // (B, H, W, C)
    const float* __restrict__ dest_offsets,  // (B, 2*K)
    const float* __restrict__ right_mat,     // (NE, NPIX)
    const float* __restrict__ L_inv,         // (NE, NE)
    const float* __restrict__ src,           // (2, K)
    float* __restrict__ out)                 // (B, H, W, C)
{
    __shared__ float s_coeff[BATCH * 2 * NE];  // [ (b*2+p)*NE + e ]

    const int tid = threadIdx.x;

    // --- einsum1: coeff[b][p][e] = sum_k (src[p][k]+off[b][p][k]) * L_inv[e][3+k]
    // products rounded individually, sequential ascending adds (no FMA).
    for (int i = tid; i < BATCH * 2 * NE; i += blockDim.x) {
        const int e  = i % NE;
        const int bp = i / NE;
        const int p  = bp & 1;
        const int b  = bp >> 1;
        float acc = 0.0f;
#pragma unroll
        for (int k = 0; k < KPTS; k++) {
            const float d = __fadd_rn(src[p * KPTS + k],
                                      dest_offsets[b * (2 * KPTS) + p * KPTS + k]);
            const float prod = __fmul_rn(d, L_inv[e * NE + 3 + k]);
            acc = __fadd_rn(acc, prod);
        }
        s_coeff[i] = acc;
    }
    __syncthreads();

    const int n = blockIdx.x * blockDim.x + tid;
    if (n >= NPIX) return;

    // right_mat column for this grid point -> registers (coalesced loads)
    float rm[NE];
#pragma unroll
    for (int e = 0; e < NE; e++) rm[e] = __ldg(&right_mat[e * NPIX + n]);

    const float fw = (float)IMG_W;
    const float fh = (float)IMG_H;

#pragma unroll 4
    for (int b = 0; b < BATCH; b++) {
        const float* cx = &s_coeff[(b * 2 + 0) * NE];
        const float* cy = &s_coeff[(b * 2 + 1) * NE];
        // einsum2: sequential ascending FMA, init 0 (cuBLAS fp32 semantics)
        float xs = 0.0f, ys = 0.0f;
#pragma unroll
        for (int e = 0; e < NE; e++) {
            xs = fmaf(cx[e], rm[e], xs);
            ys = fmaf(cy[e], rm[e], ys);
        }

        // map [-1,1] -> pixel coords (powers of two: exact)
        const float x = __fmul_rn(__fmul_rn(0.5f, __fadd_rn(xs, 1.0f)), fw);
        const float y = __fmul_rn(__fmul_rn(0.5f, __fadd_rn(ys, 1.0f)), fh);

        // trunc-toward-zero matches jnp astype(int32)
        int x0 = (int)x;
        int y0 = (int)y;
        int x1 = x0 + 1;
        int y1 = y0 + 1;
        const int x0c = min(max(x0, 0), IMG_W - 1);
        const int x1c = min(max(x1, 0), IMG_W - 1);
        const int y0c = min(max(y0, 0), IMG_H - 1);
        const int y1c = min(max(y1, 0), IMG_H - 1);

        const float x0f = (float)x0c, x1f = (float)x1c;
        const float y0f = (float)y0c, y1f = (float)y1c;
        const float wa = __fmul_rn(__fadd_rn(x1f, -x), __fadd_rn(y1f, -y));
        const float wb = __fmul_rn(__fadd_rn(x1f, -x), __fadd_rn(y, -y0f));
        const float wc = __fmul_rn(__fadd_rn(x, -x0f), __fadd_rn(y1f, -y));
        const float wd = __fmul_rn(__fadd_rn(x, -x0f), __fadd_rn(y, -y0f));

        const float* img = image + (size_t)b * (NPIX * IMG_C);
        const float* pa = img + ((size_t)y0c * IMG_W + x0c) * IMG_C;
        const float* pb = img + ((size_t)y1c * IMG_W + x0c) * IMG_C;
        const float* pc = img + ((size_t)y0c * IMG_W + x1c) * IMG_C;
        const float* pd = img + ((size_t)y1c * IMG_W + x1c) * IMG_C;

#pragma unroll
        for (int c = 0; c < IMG_C; c++) {
            // (((wa*pa + wb*pb) + wc*pc) + wd*pd), no contraction
            float o = __fmul_rn(wa, __ldg(pa + c));
            o = __fadd_rn(o, __fmul_rn(wb, __ldg(pb + c)));
            o = __fadd_rn(o, __fmul_rn(wc, __ldg(pc + c)));
            o = __fadd_rn(o, __fmul_rn(wd, __ldg(pd + c)));
            out[(size_t)b * (NPIX * IMG_C) + (size_t)n * IMG_C + c] = o;
        }
    }
}

extern "C" void kernel_launch(void* const* d_in, const int* in_sizes, int n_in,
                              void* d_out, int out_size) {
    const float* image        = (const float*)d_in[0];
    const float* dest_offsets = (const float*)d_in[1];
    const float* right_mat    = (const float*)d_in[2];
    const float* L_inv        = (const float*)d_in[3];
    const float* src          = (const float*)d_in[4];
    float* out = (float*)d_out;

    const int threads = 256;
    const int blocks  = (NPIX + threads - 1) / threads;
    tps_warp_kernel<<<blocks, threads>>>(image, dest_offsets, right_mat, L_inv, src, out);
}